// round 8
// baseline (speedup 1.0000x reference)
#include <cuda_runtime.h>
#include <math.h>
#include <stdint.h>

// Shapes
#define NB 8
#define NS 4096
#define ND 2048
#define NH 16
#define NDK 128
#define SCALE 0.08838834764831845f   // 1/sqrt(128)

typedef unsigned long long u64;

__device__ __forceinline__ void ffma2(u64& d, u64 a, u64 b) {
    asm("fma.rn.f32x2 %0, %1, %2, %0;" : "+l"(d) : "l"(a), "l"(b));
}
__device__ __forceinline__ u64 pack2(float x, float y) {
    u64 r; asm("mov.b64 %0, {%1, %2};" : "=l"(r) : "f"(x), "f"(y)); return r;
}
__device__ __forceinline__ float2 unpack2(u64 v) {
    float2 r; asm("mov.b64 {%0, %1}, %2;" : "=f"(r.x), "=f"(r.y) : "l"(v)); return r;
}
__device__ __forceinline__ uint32_t smem_u32(const void* p) {
    uint32_t a;
    asm("{ .reg .u64 t; cvta.to.shared.u64 t, %1; cvt.u32.u64 %0, t; }" : "=r"(a) : "l"(p));
    return a;
}
__device__ __forceinline__ void cpasync16(uint32_t dst, const void* src) {
    asm volatile("cp.async.cg.shared.global [%0], [%1], 16;" :: "r"(dst), "l"(src));
}
#define CP_COMMIT() asm volatile("cp.async.commit_group;" ::: "memory")
#define CP_WAIT2()  asm volatile("cp.async.wait_group 2;"  ::: "memory")

// -------- device scratch (no allocations allowed) --------
__device__ __align__(16) float g_qbp[16 * NB * ND];
__device__ __align__(16) float g_qb[NB * ND];                 // [b][h*128+d]
__device__ __align__(16) float g_A[NB * NH * ND];             // A[b][h][e]
__device__ __align__(16) float g_scores[NS * NB * NH];        // SCALE*(A.key), then += pos
__device__ float g_m[NB * NH];
__device__ float g_linv[NB * NH];
__device__ __align__(16) float g_upart[32 * NB * NH * ND];    // [jc(32)][b][h][e]
__device__ __align__(16) float g_xpart[16 * NB * ND];
__device__ __align__(16) float g_x[NB * ND];
__device__ __align__(16) float g_opart[16 * NB * ND];

// ---------------- K1: qb partials: (query @ Wq), g-split 16, MLP 8 ----------------
__global__ __launch_bounds__(256) void k_qbp(const float* __restrict__ query,
                                             const float* __restrict__ Wq) {
    int tid = threadIdx.x;
    int c   = blockIdx.x * 256 + tid;
    int g0  = blockIdx.y * 128;
    __shared__ float qs[8][128];
    for (int idx = tid; idx < 1024; idx += 256)
        qs[idx >> 7][idx & 127] = query[(idx >> 7) * ND + g0 + (idx & 127)];
    __syncthreads();
    float acc[8] = {0.f,0.f,0.f,0.f,0.f,0.f,0.f,0.f};
    for (int g = 0; g < 128; g += 8) {
        float w[8];
#pragma unroll
        for (int k2 = 0; k2 < 8; k2++) w[k2] = Wq[(g0 + g + k2) * ND + c];
#pragma unroll
        for (int k2 = 0; k2 < 8; k2++)
#pragma unroll
            for (int b = 0; b < 8; b++) acc[b] = fmaf(w[k2], qs[b][g + k2], acc[b]);
    }
#pragma unroll
    for (int b = 0; b < 8; b++) g_qbp[(blockIdx.y * 8 + b) * ND + c] = acc[b];
}

__global__ void k_qb(const float* __restrict__ q_bias) {
    int i = blockIdx.x * 256 + threadIdx.x;
    int c = i & (ND - 1);
    int b = i >> 11;
    float s = q_bias[c];
#pragma unroll
    for (int gc = 0; gc < 16; gc++) s += g_qbp[(gc * 8 + b) * ND + c];
    g_qb[i] = s;
}

// ---------------- K2: A[b][h][e] = sum_d Wk[e][h*128+d] * qb[b][h*128+d] ----------------
__global__ void k_A(const float* __restrict__ Wk) {
    int tid = threadIdx.x;           // 128
    int h   = blockIdx.y;
    int e0  = blockIdx.x * 128;
    __shared__ float qbs[8][128];
    __shared__ float wks[128][65];
    for (int idx = tid; idx < 1024; idx += 128)
        qbs[idx >> 7][idx & 127] = g_qb[(idx >> 7) * ND + h * NDK + (idx & 127)];
    float acc[8] = {0.f,0.f,0.f,0.f,0.f,0.f,0.f,0.f};
    for (int st = 0; st < 2; st++) {
        __syncthreads();
        for (int idx = tid; idx < 128 * 64; idx += 128) {
            int r = idx >> 6, cc = idx & 63;
            wks[r][cc] = Wk[(e0 + r) * ND + h * NDK + st * 64 + cc];
        }
        __syncthreads();
#pragma unroll 8
        for (int d = 0; d < 64; d++) {
            float w = wks[tid][d];
#pragma unroll
            for (int b = 0; b < 8; b++) acc[b] = fmaf(w, qbs[b][st * 64 + d], acc[b]);
        }
    }
    int e = e0 + tid;
#pragma unroll
    for (int b = 0; b < 8; b++) g_A[(b * NH + h) * ND + e] = acc[b];
}

// ---------------- K4: score pass — cp.async 4-stage key pipeline into smem ----------------
__global__ __launch_bounds__(512, 1) void k_scores(const float* __restrict__ key) {
    const int b = blockIdx.y;
    const int tid = threadIdx.x;
    const int warp = tid >> 5, lane = tid & 31;
    const int jgrp  = warp >> 1;              // 0..7 -> 4 j each
    const int hbase = (warp & 1) * 8;         // 0 or 8
    const int j0blk = blockIdx.x * 32;
    const int j0w   = j0blk + jgrp * 4;

    __shared__ __align__(16) float As[16 * 2048];     // 128 KB
    __shared__ __align__(16) float Ks[4][32 * 128];   // 64 KB, 4-stage key pipe

    const uint32_t ksb = smem_u32(Ks);

    // issue cp.async for chunk c (128 e-cols for 32 j rows) into buf c&3
    // 1024 x 16B segments; each thread does 2.
    auto issue = [&](int c) {
        if (c < 16) {
#pragma unroll
            for (int q = 0; q < 2; q++) {
                int seg = tid + q * 512;
                int j = seg >> 5, e4 = seg & 31;
                const float* src = key + ((size_t)(j0blk + j) * NB + b) * ND + c * 128 + e4 * 4;
                uint32_t dst = ksb + (uint32_t)(((c & 3) * 4096 + j * 128 + e4 * 4) * 4);
                cpasync16(dst, src);
            }
        }
        CP_COMMIT();
    };

    issue(0); issue(1); issue(2);

    // load A[b] into smem (overlaps with the async key copies)
    for (int idx = tid; idx < 8192; idx += 512)
        ((float4*)As)[idx] = ((const float4*)(g_A + (size_t)b * NH * ND))[idx];
    __syncthreads();

    u64 acc[8][4];
#pragma unroll
    for (int hh = 0; hh < 8; hh++)
#pragma unroll
        for (int jj = 0; jj < 4; jj++) acc[hh][jj] = 0ull;

    const float* apb = As + hbase * 2048 + lane * 4;

#pragma unroll 1
    for (int c = 0; c < 16; c++) {
        CP_WAIT2();
        __syncthreads();
        issue(c + 3);

        const float* kw = Ks[c & 3] + jgrp * 4 * 128 + lane * 4;
        ulonglong2 kv[4];
#pragma unroll
        for (int jj = 0; jj < 4; jj++)
            kv[jj] = *(const ulonglong2*)(kw + jj * 128);

        const float* ap = apb + c * 128;
#pragma unroll
        for (int hh = 0; hh < 8; hh++) {
            ulonglong2 a = *(const ulonglong2*)(ap + hh * 2048);
#pragma unroll
            for (int jj = 0; jj < 4; jj++) {
                ffma2(acc[hh][jj], a.x, kv[jj].x);
                ffma2(acc[hh][jj], a.y, kv[jj].y);
            }
        }
    }

    float v[32];
#pragma unroll
    for (int hh = 0; hh < 8; hh++)
#pragma unroll
        for (int jj = 0; jj < 4; jj++) {
            float2 p = unpack2(acc[hh][jj]);
            v[jj * 8 + hh] = p.x + p.y;
        }
    int n = 32;
#pragma unroll
    for (int half = 16; half >= 1; half >>= 1) {
        int m = n >> 1;
        bool upper = (lane & half) != 0;
#pragma unroll
        for (int i = 0; i < 16; i++) {
            if (i >= m) break;
            float send = upper ? v[i] : v[i + m];
            float recv = __shfl_xor_sync(0xffffffffu, send, half);
            v[i] = (upper ? v[i + m] : v[i]) + recv;
        }
        n = m;
    }
    int jj = lane >> 3, hh = lane & 7;
    g_scores[(j0w + jj) * 128 + b * 16 + hbase + hh] = v[0] * SCALE;
}

// ---------------- K3: g_scores += SCALE * (qb[b][h] . key_pos[j][h]) ----------------
__global__ __launch_bounds__(256) void k_pos(const float* __restrict__ key_pos) {
    const int warp = threadIdx.x >> 5, lane = threadIdx.x & 31;
    const int h  = blockIdx.y * 8 + warp;
    const int j0 = blockIdx.x * 4;

    u64 qb[8][2];
#pragma unroll
    for (int bb = 0; bb < 8; bb++) {
        ulonglong2 q = *(const ulonglong2*)&g_qb[bb * ND + h * NDK + lane * 4];
        qb[bb][0] = q.x; qb[bb][1] = q.y;
    }
    u64 acc[4][8];
#pragma unroll
    for (int jj = 0; jj < 4; jj++)
#pragma unroll
        for (int bb = 0; bb < 8; bb++) acc[jj][bb] = 0ull;

#pragma unroll
    for (int jj = 0; jj < 4; jj++) {
        ulonglong2 kp = *(const ulonglong2*)&key_pos[((size_t)(j0 + jj) * NH + h) * NDK + lane * 4];
#pragma unroll
        for (int bb = 0; bb < 8; bb++) {
            ffma2(acc[jj][bb], qb[bb][0], kp.x);
            ffma2(acc[jj][bb], qb[bb][1], kp.y);
        }
    }
    float v[32];
#pragma unroll
    for (int jj = 0; jj < 4; jj++)
#pragma unroll
        for (int bb = 0; bb < 8; bb++) {
            float2 p = unpack2(acc[jj][bb]);
            v[jj * 8 + bb] = p.x + p.y;
        }
    int n = 32;
#pragma unroll
    for (int half = 16; half >= 1; half >>= 1) {
        int m = n >> 1;
        bool upper = (lane & half) != 0;
#pragma unroll
        for (int i = 0; i < 16; i++) {
            if (i >= m) break;
            float send = upper ? v[i] : v[i + m];
            float recv = __shfl_xor_sync(0xffffffffu, send, half);
            v[i] = (upper ? v[i + m] : v[i]) + recv;
        }
        n = m;
    }
    int jj = lane >> 3, bb = lane & 7;
    int gi = (j0 + jj) * 128 + bb * 16 + h;
    g_scores[gi] = g_scores[gi] + v[0] * SCALE;   // accumulate pos in place
}

// ---------------- K5: softmax stats per (b,h) ----------------
__global__ void k_softmax() {
    int bh = blockIdx.x;
    int tid = threadIdx.x;
    __shared__ float red[256];
    float mx = -1e30f;
    for (int j = tid; j < NS; j += 256)
        mx = fmaxf(mx, g_scores[j * (NB * NH) + bh]);
    red[tid] = mx; __syncthreads();
    for (int s = 128; s; s >>= 1) { if (tid < s) red[tid] = fmaxf(red[tid], red[tid + s]); __syncthreads(); }
    float m = red[0]; __syncthreads();
    float sum = 0.f;
    for (int j = tid; j < NS; j += 256)
        sum += __expf(g_scores[j * (NB * NH) + bh] - m);
    red[tid] = sum; __syncthreads();
    for (int s = 128; s; s >>= 1) { if (tid < s) red[tid] += red[tid + s]; __syncthreads(); }
    if (tid == 0) { g_m[bh] = m; g_linv[bh] = 1.0f / red[0]; }
}

// ---------------- K6: value pass — float4, 4 e-cols/thread (R6 form) ----------------
__global__ __launch_bounds__(256) void k_value(const float* __restrict__ value) {
    const int tid = threadIdx.x;
    const int b = blockIdx.y, jc = blockIdx.z;
    const int e = blockIdx.x * 1024 + tid * 4;
    const int j0 = jc * 128;
    __shared__ __align__(16) u64 ws2[128 * 16];
    __shared__ float ms[16], ls[16];
    if (tid < 16) { ms[tid] = g_m[b * 16 + tid]; ls[tid] = g_linv[b * 16 + tid]; }
    __syncthreads();
    for (int idx = tid; idx < 2048; idx += 256) {
        int jl = idx >> 4, h = idx & 15;
        float w = __expf(g_scores[(j0 + jl) * 128 + b * 16 + h] - ms[h]) * ls[h];
        ws2[idx] = pack2(w, w);
    }
    __syncthreads();

    u64 acc[16][2];
#pragma unroll
    for (int h = 0; h < 16; h++) { acc[h][0] = 0ull; acc[h][1] = 0ull; }

    const float* vp = value + ((size_t)j0 * NB + b) * ND + e;
#pragma unroll 4
    for (int jl = 0; jl < 128; jl++) {
        ulonglong2 v2 = *(const ulonglong2*)(vp + (size_t)jl * (NB * ND));
        const ulonglong2* wr = (const ulonglong2*)(ws2 + jl * 16);
#pragma unroll
        for (int h2 = 0; h2 < 8; h2++) {
            ulonglong2 wp = wr[h2];
            ffma2(acc[2 * h2    ][0], wp.x, v2.x);
            ffma2(acc[2 * h2    ][1], wp.x, v2.y);
            ffma2(acc[2 * h2 + 1][0], wp.y, v2.x);
            ffma2(acc[2 * h2 + 1][1], wp.y, v2.y);
        }
    }
    int rb = (jc * 8 + b) * 16;
#pragma unroll
    for (int h = 0; h < 16; h++) {
        ulonglong2 o; o.x = acc[h][0]; o.y = acc[h][1];
        *(ulonglong2*)&g_upart[(size_t)(rb + h) * ND + e] = o;
    }
}

// ---------------- K7: x partials = u @ Wv (per head), e-split 16 ----------------
__global__ __launch_bounds__(128) void k_projv(const float* __restrict__ Wv) {
    int tid = threadIdx.x;   // 128 (= d)
    int h = blockIdx.y;
    int e0 = blockIdx.x * 128;
    __shared__ float us[8][128];
    for (int idx = tid; idx < 1024; idx += 128) {
        int bb = idx >> 7, el = idx & 127;
        float s = 0.f;
#pragma unroll
        for (int jc = 0; jc < 32; jc++)
            s += g_upart[(size_t)((jc * 8 + bb) * 16 + h) * ND + e0 + el];
        us[bb][el] = s;
    }
    __syncthreads();
    float acc[8] = {0.f,0.f,0.f,0.f,0.f,0.f,0.f,0.f};
    for (int el = 0; el < 128; el += 8) {
        float w[8];
#pragma unroll
        for (int k2 = 0; k2 < 8; k2++)
            w[k2] = Wv[(e0 + el + k2) * ND + h * NDK + tid];
#pragma unroll
        for (int k2 = 0; k2 < 8; k2++)
#pragma unroll
            for (int bb = 0; bb < 8; bb++) acc[bb] = fmaf(w[k2], us[bb][el + k2], acc[bb]);
    }
#pragma unroll
    for (int bb = 0; bb < 8; bb++)
        g_xpart[(blockIdx.x * 8 + bb) * ND + h * NDK + tid] = acc[bb];
}

__global__ void k_xred(const float* __restrict__ bv) {
    int i = blockIdx.x * 256 + threadIdx.x;
    int c = i & (ND - 1), b = i >> 11;
    float s = bv[c];
#pragma unroll
    for (int ec = 0; ec < 16; ec++) s += g_xpart[(ec * 8 + b) * ND + c];
    g_x[i] = s;
}

// ---------------- K8: out partials = x @ Wo, g-split 16, MLP 8 ----------------
__global__ __launch_bounds__(256) void k_out(const float* __restrict__ Wo) {
    int tid = threadIdx.x;
    int f = blockIdx.x * 256 + tid;
    int g0 = blockIdx.y * 128;
    __shared__ float xs[8][128];
    for (int idx = tid; idx < 1024; idx += 256)
        xs[idx >> 7][idx & 127] = g_x[(idx >> 7) * ND + g0 + (idx & 127)];
    __syncthreads();
    float acc[8] = {0.f,0.f,0.f,0.f,0.f,0.f,0.f,0.f};
    for (int g = 0; g < 128; g += 8) {
        float w[8];
#pragma unroll
        for (int k2 = 0; k2 < 8; k2++) w[k2] = Wo[(g0 + g + k2) * ND + f];
#pragma unroll
        for (int k2 = 0; k2 < 8; k2++)
#pragma unroll
            for (int b = 0; b < 8; b++) acc[b] = fmaf(w[k2], xs[b][g + k2], acc[b]);
    }
#pragma unroll
    for (int b = 0; b < 8; b++) g_opart[(blockIdx.y * 8 + b) * ND + f] = acc[b];
}

__global__ void k_ored(const float* __restrict__ bo, float* __restrict__ out) {
    int i = blockIdx.x * 256 + threadIdx.x;
    int c = i & (ND - 1), b = i >> 11;
    float s = bo[c];
#pragma unroll
    for (int gc = 0; gc < 16; gc++) s += g_opart[(gc * 8 + b) * ND + c];
    out[i] = s;
}

extern "C" void kernel_launch(void* const* d_in, const int* in_sizes, int n_in,
                              void* d_out, int out_size) {
    const float* query   = (const float*)d_in[0];
    const float* key     = (const float*)d_in[1];
    const float* value   = (const float*)d_in[2];
    const float* Wq      = (const float*)d_in[3];
    const float* Wk      = (const float*)d_in[4];
    const float* Wv      = (const float*)d_in[5];
    const float* bv      = (const float*)d_in[6];
    const float* Wo      = (const float*)d_in[7];
    const float* bo      = (const float*)d_in[8];
    const float* key_pos = (const float*)d_in[9];
    const float* q_bias  = (const float*)d_in[10];
    float* out = (float*)d_out;

    // k_scores kept at launch idx 3 so the profiler's fixed slot lands on it.
    k_qbp    <<<dim3(8, 16),     256>>>(query, Wq);
    k_qb     <<<64,              256>>>(q_bias);
    k_A      <<<dim3(16, 16),    128>>>(Wk);
    k_scores <<<dim3(128, 8),    512>>>(key);
    k_pos    <<<dim3(1024, 2),   256>>>(key_pos);
    k_softmax<<<128,             256>>>();
    k_value  <<<dim3(2, 8, 32),  256>>>(value);
    k_projv  <<<dim3(16, 16),    128>>>(Wv);
    k_xred   <<<64,              256>>>(bv);
    k_out    <<<dim3(8, 16),     256>>>(Wo);
    k_ored   <<<64,              256>>>(bo, out);
}

// round 9
// speedup vs baseline: 1.0932x; 1.0932x over previous
#include <cuda_runtime.h>
#include <math.h>
#include <stdint.h>

// Shapes
#define NB 8
#define NS 4096
#define ND 2048
#define NH 16
#define NDK 128
#define SCALE 0.08838834764831845f   // 1/sqrt(128)

typedef unsigned long long u64;

__device__ __forceinline__ void ffma2(u64& d, u64 a, u64 b) {
    asm("fma.rn.f32x2 %0, %1, %2, %0;" : "+l"(d) : "l"(a), "l"(b));
}
__device__ __forceinline__ u64 pack2(float x, float y) {
    u64 r; asm("mov.b64 %0, {%1, %2};" : "=l"(r) : "f"(x), "f"(y)); return r;
}
__device__ __forceinline__ float2 unpack2(u64 v) {
    float2 r; asm("mov.b64 {%0, %1}, %2;" : "=f"(r.x), "=f"(r.y) : "l"(v)); return r;
}

// -------- device scratch (no allocations allowed) --------
__device__ __align__(16) float g_qbp[16 * NB * ND];
__device__ __align__(16) float g_qb[NB * ND];                 // [b][h*128+d]
__device__ __align__(16) float g_A[NB * NH * ND];             // A[b][h][e]
__device__ __align__(16) float g_scores[NS * NB * NH];        // SCALE*(A.key), then += pos
__device__ float g_m[NB * NH];
__device__ float g_linv[NB * NH];
__device__ __align__(16) float g_upart[32 * NB * NH * ND];    // [jc(32)][b][h][e]
__device__ __align__(16) float g_xpart[16 * NB * ND];
__device__ __align__(16) float g_x[NB * ND];
__device__ __align__(16) float g_opart[16 * NB * ND];

// ---------------- K1: qb partials: (query @ Wq), g-split 16, MLP 8 ----------------
__global__ __launch_bounds__(256) void k_qbp(const float* __restrict__ query,
                                             const float* __restrict__ Wq) {
    int tid = threadIdx.x;
    int c   = blockIdx.x * 256 + tid;
    int g0  = blockIdx.y * 128;
    __shared__ float qs[8][128];
    for (int idx = tid; idx < 1024; idx += 256)
        qs[idx >> 7][idx & 127] = query[(idx >> 7) * ND + g0 + (idx & 127)];
    __syncthreads();
    float acc[8] = {0.f,0.f,0.f,0.f,0.f,0.f,0.f,0.f};
    for (int g = 0; g < 128; g += 8) {
        float w[8];
#pragma unroll
        for (int k2 = 0; k2 < 8; k2++) w[k2] = Wq[(g0 + g + k2) * ND + c];
#pragma unroll
        for (int k2 = 0; k2 < 8; k2++)
#pragma unroll
            for (int b = 0; b < 8; b++) acc[b] = fmaf(w[k2], qs[b][g + k2], acc[b]);
    }
#pragma unroll
    for (int b = 0; b < 8; b++) g_qbp[(blockIdx.y * 8 + b) * ND + c] = acc[b];
}

__global__ void k_qb(const float* __restrict__ q_bias) {
    int i = blockIdx.x * 256 + threadIdx.x;
    int c = i & (ND - 1);
    int b = i >> 11;
    float s = q_bias[c];
#pragma unroll
    for (int gc = 0; gc < 16; gc++) s += g_qbp[(gc * 8 + b) * ND + c];
    g_qb[i] = s;
}

// ---------------- K2: A[b][h][e] = sum_d Wk[e][h*128+d] * qb[b][h*128+d] ----------------
__global__ void k_A(const float* __restrict__ Wk) {
    int tid = threadIdx.x;           // 128
    int h   = blockIdx.y;
    int e0  = blockIdx.x * 128;
    __shared__ float qbs[8][128];
    __shared__ float wks[128][65];
    for (int idx = tid; idx < 1024; idx += 128)
        qbs[idx >> 7][idx & 127] = g_qb[(idx >> 7) * ND + h * NDK + (idx & 127)];
    float acc[8] = {0.f,0.f,0.f,0.f,0.f,0.f,0.f,0.f};
    for (int st = 0; st < 2; st++) {
        __syncthreads();
        for (int idx = tid; idx < 128 * 64; idx += 128) {
            int r = idx >> 6, cc = idx & 63;
            wks[r][cc] = Wk[(e0 + r) * ND + h * NDK + st * 64 + cc];
        }
        __syncthreads();
#pragma unroll 8
        for (int d = 0; d < 64; d++) {
            float w = wks[tid][d];
#pragma unroll
            for (int b = 0; b < 8; b++) acc[b] = fmaf(w, qbs[b][st * 64 + d], acc[b]);
        }
    }
    int e = e0 + tid;
#pragma unroll
    for (int b = 0; b < 8; b++) g_A[(b * NH + h) * ND + e] = acc[b];
}

// ---------------- K4: score pass — warp tile (4h x 8j), no spills ----------------
__global__ __launch_bounds__(512, 1) void k_scores(const float* __restrict__ key) {
    const int b = blockIdx.y;
    const int tid = threadIdx.x;
    const int warp = tid >> 5, lane = tid & 31;
    const int jgrp  = warp & 3;               // 4 jgroups x 8 j = 32 j  (== SMSP id)
    const int hbase = (warp >> 2) * 4;        // 4 hgroups x 4 h
    const int j0w = blockIdx.x * 32 + jgrp * 8;

    __shared__ __align__(16) float As[16 * 2048];   // 128 KB
    for (int idx = tid; idx < 8192; idx += 512)
        ((float4*)As)[idx] = ((const float4*)(g_A + (size_t)b * NH * ND))[idx];
    __syncthreads();

    u64 acc[4][8];
#pragma unroll
    for (int hh = 0; hh < 4; hh++)
#pragma unroll
        for (int jj = 0; jj < 8; jj++) acc[hh][jj] = 0ull;

    const float* kbase = key + ((size_t)j0w * NB + b) * ND + lane * 4;
    const float* apb   = As + hbase * 2048 + lane * 4;

#pragma unroll 1
    for (int c = 0; c < 16; c++) {
        ulonglong2 kv[8];
#pragma unroll
        for (int jj = 0; jj < 8; jj++)
            kv[jj] = *(const ulonglong2*)(kbase + (size_t)jj * (NB * ND) + c * 128);
        const float* ap = apb + c * 128;
#pragma unroll
        for (int hh = 0; hh < 4; hh++) {
            ulonglong2 a = *(const ulonglong2*)(ap + hh * 2048);
#pragma unroll
            for (int jj = 0; jj < 8; jj++) {
                ffma2(acc[hh][jj], a.x, kv[jj].x);
                ffma2(acc[hh][jj], a.y, kv[jj].y);
            }
        }
    }

    // 32 values per warp: v[jj*4 + hh]
    float v[32];
#pragma unroll
    for (int hh = 0; hh < 4; hh++)
#pragma unroll
        for (int jj = 0; jj < 8; jj++) {
            float2 p = unpack2(acc[hh][jj]);
            v[jj * 4 + hh] = p.x + p.y;
        }
    int n = 32;
#pragma unroll
    for (int half = 16; half >= 1; half >>= 1) {
        int m = n >> 1;
        bool upper = (lane & half) != 0;
#pragma unroll
        for (int i = 0; i < 16; i++) {
            if (i >= m) break;
            float send = upper ? v[i] : v[i + m];
            float recv = __shfl_xor_sync(0xffffffffu, send, half);
            v[i] = (upper ? v[i + m] : v[i]) + recv;
        }
        n = m;
    }
    int jj = lane >> 2, hh = lane & 3;
    g_scores[(j0w + jj) * 128 + b * 16 + hbase + hh] = v[0] * SCALE;
}

// ---------------- K3: g_scores += SCALE * (qb[b][h] . key_pos[j][h]) ----------------
__global__ __launch_bounds__(256) void k_pos(const float* __restrict__ key_pos) {
    const int warp = threadIdx.x >> 5, lane = threadIdx.x & 31;
    const int h  = blockIdx.y * 8 + warp;
    const int j0 = blockIdx.x * 4;

    u64 qb[8][2];
#pragma unroll
    for (int bb = 0; bb < 8; bb++) {
        ulonglong2 q = *(const ulonglong2*)&g_qb[bb * ND + h * NDK + lane * 4];
        qb[bb][0] = q.x; qb[bb][1] = q.y;
    }
    u64 acc[4][8];
#pragma unroll
    for (int jj = 0; jj < 4; jj++)
#pragma unroll
        for (int bb = 0; bb < 8; bb++) acc[jj][bb] = 0ull;

#pragma unroll
    for (int jj = 0; jj < 4; jj++) {
        ulonglong2 kp = *(const ulonglong2*)&key_pos[((size_t)(j0 + jj) * NH + h) * NDK + lane * 4];
#pragma unroll
        for (int bb = 0; bb < 8; bb++) {
            ffma2(acc[jj][bb], qb[bb][0], kp.x);
            ffma2(acc[jj][bb], qb[bb][1], kp.y);
        }
    }
    float v[32];
#pragma unroll
    for (int jj = 0; jj < 4; jj++)
#pragma unroll
        for (int bb = 0; bb < 8; bb++) {
            float2 p = unpack2(acc[jj][bb]);
            v[jj * 8 + bb] = p.x + p.y;
        }
    int n = 32;
#pragma unroll
    for (int half = 16; half >= 1; half >>= 1) {
        int m = n >> 1;
        bool upper = (lane & half) != 0;
#pragma unroll
        for (int i = 0; i < 16; i++) {
            if (i >= m) break;
            float send = upper ? v[i] : v[i + m];
            float recv = __shfl_xor_sync(0xffffffffu, send, half);
            v[i] = (upper ? v[i + m] : v[i]) + recv;
        }
        n = m;
    }
    int jj = lane >> 3, bb = lane & 7;
    int gi = (j0 + jj) * 128 + bb * 16 + h;
    g_scores[gi] = g_scores[gi] + v[0] * SCALE;   // accumulate pos in place
}

// ---------------- K5: softmax stats per (b,h) ----------------
__global__ void k_softmax() {
    int bh = blockIdx.x;
    int tid = threadIdx.x;
    __shared__ float red[256];
    float mx = -1e30f;
    for (int j = tid; j < NS; j += 256)
        mx = fmaxf(mx, g_scores[j * (NB * NH) + bh]);
    red[tid] = mx; __syncthreads();
    for (int s = 128; s; s >>= 1) { if (tid < s) red[tid] = fmaxf(red[tid], red[tid + s]); __syncthreads(); }
    float m = red[0]; __syncthreads();
    float sum = 0.f;
    for (int j = tid; j < NS; j += 256)
        sum += __expf(g_scores[j * (NB * NH) + bh] - m);
    red[tid] = sum; __syncthreads();
    for (int s = 128; s; s >>= 1) { if (tid < s) red[tid] += red[tid + s]; __syncthreads(); }
    if (tid == 0) { g_m[bh] = m; g_linv[bh] = 1.0f / red[0]; }
}

// ---------------- K6: value pass — 4 e-cols/thread, 8-deep batched loads ----------------
__global__ __launch_bounds__(256) void k_value(const float* __restrict__ value) {
    const int tid = threadIdx.x;
    const int b = blockIdx.y, jc = blockIdx.z;
    const int e = blockIdx.x * 1024 + tid * 4;
    const int j0 = jc * 128;
    __shared__ __align__(16) u64 ws2[128 * 16];
    __shared__ float ms[16], ls[16];
    if (tid < 16) { ms[tid] = g_m[b * 16 + tid]; ls[tid] = g_linv[b * 16 + tid]; }
    __syncthreads();
    for (int idx = tid; idx < 2048; idx += 256) {
        int jl = idx >> 4, h = idx & 15;
        float w = __expf(g_scores[(j0 + jl) * 128 + b * 16 + h] - ms[h]) * ls[h];
        ws2[idx] = pack2(w, w);
    }
    __syncthreads();

    u64 acc[16][2];
#pragma unroll
    for (int h = 0; h < 16; h++) { acc[h][0] = 0ull; acc[h][1] = 0ull; }

    const float* vp = value + ((size_t)j0 * NB + b) * ND + e;
    const size_t jstride = (size_t)NB * ND;

#pragma unroll 1
    for (int jl = 0; jl < 128; jl += 8) {
        ulonglong2 v2[8];
#pragma unroll
        for (int k2 = 0; k2 < 8; k2++)
            v2[k2] = *(const ulonglong2*)(vp + (size_t)(jl + k2) * jstride);
#pragma unroll
        for (int k2 = 0; k2 < 8; k2++) {
            const ulonglong2* wr = (const ulonglong2*)(ws2 + (jl + k2) * 16);
#pragma unroll
            for (int h2 = 0; h2 < 8; h2++) {
                ulonglong2 wp = wr[h2];
                ffma2(acc[2 * h2    ][0], wp.x, v2[k2].x);
                ffma2(acc[2 * h2    ][1], wp.x, v2[k2].y);
                ffma2(acc[2 * h2 + 1][0], wp.y, v2[k2].x);
                ffma2(acc[2 * h2 + 1][1], wp.y, v2[k2].y);
            }
        }
    }
    int rb = (jc * 8 + b) * 16;
#pragma unroll
    for (int h = 0; h < 16; h++) {
        ulonglong2 o; o.x = acc[h][0]; o.y = acc[h][1];
        *(ulonglong2*)&g_upart[(size_t)(rb + h) * ND + e] = o;
    }
}

// ---------------- K7: x partials = u @ Wv (per head), e-split 16 ----------------
__global__ __launch_bounds__(128) void k_projv(const float* __restrict__ Wv) {
    int tid = threadIdx.x;   // 128 (= d)
    int h = blockIdx.y;
    int e0 = blockIdx.x * 128;
    __shared__ float us[8][128];
    for (int idx = tid; idx < 1024; idx += 128) {
        int bb = idx >> 7, el = idx & 127;
        float s = 0.f;
#pragma unroll
        for (int jc = 0; jc < 32; jc++)
            s += g_upart[(size_t)((jc * 8 + bb) * 16 + h) * ND + e0 + el];
        us[bb][el] = s;
    }
    __syncthreads();
    float acc[8] = {0.f,0.f,0.f,0.f,0.f,0.f,0.f,0.f};
    for (int el = 0; el < 128; el += 8) {
        float w[8];
#pragma unroll
        for (int k2 = 0; k2 < 8; k2++)
            w[k2] = Wv[(e0 + el + k2) * ND + h * NDK + tid];
#pragma unroll
        for (int k2 = 0; k2 < 8; k2++)
#pragma unroll
            for (int bb = 0; bb < 8; bb++) acc[bb] = fmaf(w[k2], us[bb][el + k2], acc[bb]);
    }
#pragma unroll
    for (int bb = 0; bb < 8; bb++)
        g_xpart[(blockIdx.x * 8 + bb) * ND + h * NDK + tid] = acc[bb];
}

__global__ void k_xred(const float* __restrict__ bv) {
    int i = blockIdx.x * 256 + threadIdx.x;
    int c = i & (ND - 1), b = i >> 11;
    float s = bv[c];
#pragma unroll
    for (int ec = 0; ec < 16; ec++) s += g_xpart[(ec * 8 + b) * ND + c];
    g_x[i] = s;
}

// ---------------- K8: out partials = x @ Wo, g-split 16, MLP 8 ----------------
__global__ __launch_bounds__(256) void k_out(const float* __restrict__ Wo) {
    int tid = threadIdx.x;
    int f = blockIdx.x * 256 + tid;
    int g0 = blockIdx.y * 128;
    __shared__ float xs[8][128];
    for (int idx = tid; idx < 1024; idx += 256)
        xs[idx >> 7][idx & 127] = g_x[(idx >> 7) * ND + g0 + (idx & 127)];
    __syncthreads();
    float acc[8] = {0.f,0.f,0.f,0.f,0.f,0.f,0.f,0.f};
    for (int g = 0; g < 128; g += 8) {
        float w[8];
#pragma unroll
        for (int k2 = 0; k2 < 8; k2++) w[k2] = Wo[(g0 + g + k2) * ND + f];
#pragma unroll
        for (int k2 = 0; k2 < 8; k2++)
#pragma unroll
            for (int b = 0; b < 8; b++) acc[b] = fmaf(w[k2], xs[b][g + k2], acc[b]);
    }
#pragma unroll
    for (int b = 0; b < 8; b++) g_opart[(blockIdx.y * 8 + b) * ND + f] = acc[b];
}

__global__ void k_ored(const float* __restrict__ bo, float* __restrict__ out) {
    int i = blockIdx.x * 256 + threadIdx.x;
    int c = i & (ND - 1), b = i >> 11;
    float s = bo[c];
#pragma unroll
    for (int gc = 0; gc < 16; gc++) s += g_opart[(gc * 8 + b) * ND + c];
    out[i] = s;
}

extern "C" void kernel_launch(void* const* d_in, const int* in_sizes, int n_in,
                              void* d_out, int out_size) {
    const float* query   = (const float*)d_in[0];
    const float* key     = (const float*)d_in[1];
    const float* value   = (const float*)d_in[2];
    const float* Wq      = (const float*)d_in[3];
    const float* Wk      = (const float*)d_in[4];
    const float* Wv      = (const float*)d_in[5];
    const float* bv      = (const float*)d_in[6];
    const float* Wo      = (const float*)d_in[7];
    const float* bo      = (const float*)d_in[8];
    const float* key_pos = (const float*)d_in[9];
    const float* q_bias  = (const float*)d_in[10];
    float* out = (float*)d_out;

    // k_scores kept at launch idx 3 so the profiler's fixed slot lands on it.
    k_qbp    <<<dim3(8, 16),     256>>>(query, Wq);
    k_qb     <<<64,              256>>>(q_bias);
    k_A      <<<dim3(16, 16),    128>>>(Wk);
    k_scores <<<dim3(128, 8),    512>>>(key);
    k_pos    <<<dim3(1024, 2),   256>>>(key_pos);
    k_softmax<<<128,             256>>>();
    k_value  <<<dim3(2, 8, 32),  256>>>(value);
    k_projv  <<<dim3(16, 16),    128>>>(Wv);
    k_xred   <<<64,              256>>>(bv);
    k_out    <<<dim3(8, 16),     256>>>(Wo);
    k_ored   <<<64,              256>>>(bo, out);
}

// round 10
// speedup vs baseline: 1.2433x; 1.1373x over previous
#include <cuda_runtime.h>
#include <math.h>
#include <stdint.h>

// Shapes
#define NB 8
#define NS 4096
#define ND 2048
#define NH 16
#define NDK 128
#define SCALE 0.08838834764831845f   // 1/sqrt(128)

typedef unsigned long long u64;

__device__ __forceinline__ void ffma2(u64& d, u64 a, u64 b) {
    asm("fma.rn.f32x2 %0, %1, %2, %0;" : "+l"(d) : "l"(a), "l"(b));
}
__device__ __forceinline__ u64 pack2(float x, float y) {
    u64 r; asm("mov.b64 %0, {%1, %2};" : "=l"(r) : "f"(x), "f"(y)); return r;
}
__device__ __forceinline__ float2 unpack2(u64 v) {
    float2 r; asm("mov.b64 {%0, %1}, %2;" : "=f"(r.x), "=f"(r.y) : "l"(v)); return r;
}
__device__ __forceinline__ uint32_t smem_u32(const void* p) {
    uint32_t a;
    asm("{ .reg .u64 t; cvta.to.shared.u64 t, %1; cvt.u32.u64 %0, t; }" : "=r"(a) : "l"(p));
    return a;
}
__device__ __forceinline__ void cpasync16(uint32_t dst, const void* src) {
    asm volatile("cp.async.cg.shared.global [%0], [%1], 16;" :: "r"(dst), "l"(src));
}
#define CP_COMMIT() asm volatile("cp.async.commit_group;" ::: "memory")

// -------- device scratch (no allocations allowed) --------
__device__ __align__(16) float g_qbp[16 * NB * ND];
__device__ __align__(16) float g_qb[NB * ND];                 // [b][h*128+d]
__device__ __align__(16) float g_A[NB * NH * ND];             // A[b][h][e]
__device__ __align__(16) float g_scores[NS * NB * NH];        // SCALE*(A.key), then += pos
__device__ float g_m[NB * NH];
__device__ float g_linv[NB * NH];
__device__ __align__(16) float g_upart[32 * NB * NH * ND];    // [jc(32)][b][h][e]
__device__ __align__(16) float g_xpart[16 * NB * ND];
__device__ __align__(16) float g_x[NB * ND];
__device__ __align__(16) float g_opart[16 * NB * ND];

// ---------------- K1: qb partials: (query @ Wq), g-split 16, MLP 8 ----------------
__global__ __launch_bounds__(256) void k_qbp(const float* __restrict__ query,
                                             const float* __restrict__ Wq) {
    int tid = threadIdx.x;
    int c   = blockIdx.x * 256 + tid;
    int g0  = blockIdx.y * 128;
    __shared__ float qs[8][128];
    for (int idx = tid; idx < 1024; idx += 256)
        qs[idx >> 7][idx & 127] = query[(idx >> 7) * ND + g0 + (idx & 127)];
    __syncthreads();
    float acc[8] = {0.f,0.f,0.f,0.f,0.f,0.f,0.f,0.f};
    for (int g = 0; g < 128; g += 8) {
        float w[8];
#pragma unroll
        for (int k2 = 0; k2 < 8; k2++) w[k2] = Wq[(g0 + g + k2) * ND + c];
#pragma unroll
        for (int k2 = 0; k2 < 8; k2++)
#pragma unroll
            for (int b = 0; b < 8; b++) acc[b] = fmaf(w[k2], qs[b][g + k2], acc[b]);
    }
#pragma unroll
    for (int b = 0; b < 8; b++) g_qbp[(blockIdx.y * 8 + b) * ND + c] = acc[b];
}

__global__ void k_qb(const float* __restrict__ q_bias) {
    int i = blockIdx.x * 256 + threadIdx.x;
    int c = i & (ND - 1);
    int b = i >> 11;
    float s = q_bias[c];
#pragma unroll
    for (int gc = 0; gc < 16; gc++) s += g_qbp[(gc * 8 + b) * ND + c];
    g_qb[i] = s;
}

// ---------------- K2: A[b][h][e] = sum_d Wk[e][h*128+d] * qb[b][h*128+d] ----------------
__global__ void k_A(const float* __restrict__ Wk) {
    int tid = threadIdx.x;           // 128
    int h   = blockIdx.y;
    int e0  = blockIdx.x * 128;
    __shared__ float qbs[8][128];
    __shared__ float wks[128][65];
    for (int idx = tid; idx < 1024; idx += 128)
        qbs[idx >> 7][idx & 127] = g_qb[(idx >> 7) * ND + h * NDK + (idx & 127)];
    float acc[8] = {0.f,0.f,0.f,0.f,0.f,0.f,0.f,0.f};
    for (int st = 0; st < 2; st++) {
        __syncthreads();
        for (int idx = tid; idx < 128 * 64; idx += 128) {
            int r = idx >> 6, cc = idx & 63;
            wks[r][cc] = Wk[(e0 + r) * ND + h * NDK + st * 64 + cc];
        }
        __syncthreads();
#pragma unroll 8
        for (int d = 0; d < 64; d++) {
            float w = wks[tid][d];
#pragma unroll
            for (int b = 0; b < 8; b++) acc[b] = fmaf(w, qbs[b][st * 64 + d], acc[b]);
        }
    }
    int e = e0 + tid;
#pragma unroll
    for (int b = 0; b < 8; b++) g_A[(b * NH + h) * ND + e] = acc[b];
}

// ---------------- K4: score pass — R6 tile (8h x 4j) + per-pair cp.async ring ----------------
__global__ __launch_bounds__(512, 1) void k_scores(const float* __restrict__ key) {
    const int b = blockIdx.y;
    const int tid = threadIdx.x;
    const int warp = tid >> 5, lane = tid & 31;
    const int jgrp  = warp >> 1;              // 8 pairs, 4 j each
    const int hbase = (warp & 1) * 8;         // pair member: h-half
    const int j0w = blockIdx.x * 32 + jgrp * 4;
    // producer parity spread over all 4 SMSPs: warps 0,2,5,7,8,10,13,15
    const bool is_prod = ((warp & 1) == ((warp >> 2) & 1));
    const int barid = 1 + jgrp;               // named barriers 1..8

    __shared__ __align__(16) float As[16 * 2048];   // 128 KB
    __shared__ __align__(16) float Kr[8][3][512];   // 48 KB: per-pair 3-stage ring

    const int krow = lane >> 3;               // 0..3 (j row within group)
    const int kcol = lane & 7;                // 0..7 (16B column)
    const float* ksrc = key + ((size_t)(j0w + krow) * NB + b) * ND + kcol * 4;
    const uint32_t ringb = smem_u32(&Kr[jgrp][0][0]) + (uint32_t)(krow * 512 + kcol * 16);

    // producer prologue: stage chunks 0..2
    if (is_prod) {
#pragma unroll
        for (int c = 0; c < 3; c++) {
            uint32_t d0 = ringb + (uint32_t)(c * 2048);
            const float* s0 = ksrc + c * 128;
#pragma unroll
            for (int s = 0; s < 4; s++)
                cpasync16(d0 + s * 128, s0 + s * 32);
            CP_COMMIT();
        }
    }

    // load A[b] into smem (overlaps the async key staging)
    for (int idx = tid; idx < 8192; idx += 512)
        ((float4*)As)[idx] = ((const float4*)(g_A + (size_t)b * NH * ND))[idx];
    __syncthreads();

    u64 acc[8][4];
#pragma unroll
    for (int hh = 0; hh < 8; hh++)
#pragma unroll
        for (int jj = 0; jj < 4; jj++) acc[hh][jj] = 0ull;

    const float* apb = As + hbase * 2048 + lane * 4;
    const float* kwb = &Kr[jgrp][0][0] + lane * 4;

#pragma unroll 1
    for (int c = 0; c < 16; c++) {
        if (is_prod) asm volatile("cp.async.wait_group 2;" ::: "memory");
        asm volatile("bar.sync %0, 64;" :: "r"(barid) : "memory");   // data ready

        const float* kw = kwb + (c % 3) * 512;
        ulonglong2 kv[4];
#pragma unroll
        for (int jj = 0; jj < 4; jj++)
            kv[jj] = *(const ulonglong2*)(kw + jj * 128);

        const float* ap = apb + c * 128;
#pragma unroll
        for (int hh = 0; hh < 8; hh++) {
            ulonglong2 a = *(const ulonglong2*)(ap + hh * 2048);
#pragma unroll
            for (int jj = 0; jj < 4; jj++) {
                ffma2(acc[hh][jj], a.x, kv[jj].x);
                ffma2(acc[hh][jj], a.y, kv[jj].y);
            }
        }

        asm volatile("bar.sync %0, 64;" :: "r"(barid) : "memory");   // buffer free
        if (is_prod) {
            int cn = c + 3;
            if (cn < 16) {
                uint32_t d0 = ringb + (uint32_t)((cn % 3) * 2048);
                const float* s0 = ksrc + cn * 128;
#pragma unroll
                for (int s = 0; s < 4; s++)
                    cpasync16(d0 + s * 128, s0 + s * 32);
            }
            CP_COMMIT();
        }
    }

    // 32 values per warp: v[jj*8 + hh]
    float v[32];
#pragma unroll
    for (int hh = 0; hh < 8; hh++)
#pragma unroll
        for (int jj = 0; jj < 4; jj++) {
            float2 p = unpack2(acc[hh][jj]);
            v[jj * 8 + hh] = p.x + p.y;
        }
    int n = 32;
#pragma unroll
    for (int half = 16; half >= 1; half >>= 1) {
        int m = n >> 1;
        bool upper = (lane & half) != 0;
#pragma unroll
        for (int i = 0; i < 16; i++) {
            if (i >= m) break;
            float send = upper ? v[i] : v[i + m];
            float recv = __shfl_xor_sync(0xffffffffu, send, half);
            v[i] = (upper ? v[i + m] : v[i]) + recv;
        }
        n = m;
    }
    int jj = lane >> 3, hh = lane & 7;
    g_scores[(j0w + jj) * 128 + b * 16 + hbase + hh] = v[0] * SCALE;
}

// ---------------- K3: g_scores += SCALE * (qb[b][h] . key_pos[j][h]) ----------------
__global__ __launch_bounds__(256) void k_pos(const float* __restrict__ key_pos) {
    const int warp = threadIdx.x >> 5, lane = threadIdx.x & 31;
    const int h  = blockIdx.y * 8 + warp;
    const int j0 = blockIdx.x * 4;

    u64 qb[8][2];
#pragma unroll
    for (int bb = 0; bb < 8; bb++) {
        ulonglong2 q = *(const ulonglong2*)&g_qb[bb * ND + h * NDK + lane * 4];
        qb[bb][0] = q.x; qb[bb][1] = q.y;
    }
    u64 acc[4][8];
#pragma unroll
    for (int jj = 0; jj < 4; jj++)
#pragma unroll
        for (int bb = 0; bb < 8; bb++) acc[jj][bb] = 0ull;

#pragma unroll
    for (int jj = 0; jj < 4; jj++) {
        ulonglong2 kp = *(const ulonglong2*)&key_pos[((size_t)(j0 + jj) * NH + h) * NDK + lane * 4];
#pragma unroll
        for (int bb = 0; bb < 8; bb++) {
            ffma2(acc[jj][bb], qb[bb][0], kp.x);
            ffma2(acc[jj][bb], qb[bb][1], kp.y);
        }
    }
    float v[32];
#pragma unroll
    for (int jj = 0; jj < 4; jj++)
#pragma unroll
        for (int bb = 0; bb < 8; bb++) {
            float2 p = unpack2(acc[jj][bb]);
            v[jj * 8 + bb] = p.x + p.y;
        }
    int n = 32;
#pragma unroll
    for (int half = 16; half >= 1; half >>= 1) {
        int m = n >> 1;
        bool upper = (lane & half) != 0;
#pragma unroll
        for (int i = 0; i < 16; i++) {
            if (i >= m) break;
            float send = upper ? v[i] : v[i + m];
            float recv = __shfl_xor_sync(0xffffffffu, send, half);
            v[i] = (upper ? v[i + m] : v[i]) + recv;
        }
        n = m;
    }
    int jj = lane >> 3, bb = lane & 7;
    int gi = (j0 + jj) * 128 + bb * 16 + h;
    g_scores[gi] = g_scores[gi] + v[0] * SCALE;   // accumulate pos in place
}

// ---------------- K5: softmax stats per (b,h) ----------------
__global__ void k_softmax() {
    int bh = blockIdx.x;
    int tid = threadIdx.x;
    __shared__ float red[256];
    float mx = -1e30f;
    for (int j = tid; j < NS; j += 256)
        mx = fmaxf(mx, g_scores[j * (NB * NH) + bh]);
    red[tid] = mx; __syncthreads();
    for (int s = 128; s; s >>= 1) { if (tid < s) red[tid] = fmaxf(red[tid], red[tid + s]); __syncthreads(); }
    float m = red[0]; __syncthreads();
    float sum = 0.f;
    for (int j = tid; j < NS; j += 256)
        sum += __expf(g_scores[j * (NB * NH) + bh] - m);
    red[tid] = sum; __syncthreads();
    for (int s = 128; s; s >>= 1) { if (tid < s) red[tid] += red[tid + s]; __syncthreads(); }
    if (tid == 0) { g_m[bh] = m; g_linv[bh] = 1.0f / red[0]; }
}

// ---------------- K6: value pass — float4, 4 e-cols/thread (R6 form) ----------------
__global__ __launch_bounds__(256) void k_value(const float* __restrict__ value) {
    const int tid = threadIdx.x;
    const int b = blockIdx.y, jc = blockIdx.z;
    const int e = blockIdx.x * 1024 + tid * 4;
    const int j0 = jc * 128;
    __shared__ __align__(16) u64 ws2[128 * 16];
    __shared__ float ms[16], ls[16];
    if (tid < 16) { ms[tid] = g_m[b * 16 + tid]; ls[tid] = g_linv[b * 16 + tid]; }
    __syncthreads();
    for (int idx = tid; idx < 2048; idx += 256) {
        int jl = idx >> 4, h = idx & 15;
        float w = __expf(g_scores[(j0 + jl) * 128 + b * 16 + h] - ms[h]) * ls[h];
        ws2[idx] = pack2(w, w);
    }
    __syncthreads();

    u64 acc[16][2];
#pragma unroll
    for (int h = 0; h < 16; h++) { acc[h][0] = 0ull; acc[h][1] = 0ull; }

    const float* vp = value + ((size_t)j0 * NB + b) * ND + e;
#pragma unroll 4
    for (int jl = 0; jl < 128; jl++) {
        ulonglong2 v2 = *(const ulonglong2*)(vp + (size_t)jl * (NB * ND));
        const ulonglong2* wr = (const ulonglong2*)(ws2 + jl * 16);
#pragma unroll
        for (int h2 = 0; h2 < 8; h2++) {
            ulonglong2 wp = wr[h2];
            ffma2(acc[2 * h2    ][0], wp.x, v2.x);
            ffma2(acc[2 * h2    ][1], wp.x, v2.y);
            ffma2(acc[2 * h2 + 1][0], wp.y, v2.x);
            ffma2(acc[2 * h2 + 1][1], wp.y, v2.y);
        }
    }
    int rb = (jc * 8 + b) * 16;
#pragma unroll
    for (int h = 0; h < 16; h++) {
        ulonglong2 o; o.x = acc[h][0]; o.y = acc[h][1];
        *(ulonglong2*)&g_upart[(size_t)(rb + h) * ND + e] = o;
    }
}

// ---------------- K7: x partials = u @ Wv (per head), e-split 16 ----------------
__global__ __launch_bounds__(128) void k_projv(const float* __restrict__ Wv) {
    int tid = threadIdx.x;   // 128 (= d)
    int h = blockIdx.y;
    int e0 = blockIdx.x * 128;
    __shared__ float us[8][128];
    for (int idx = tid; idx < 1024; idx += 128) {
        int bb = idx >> 7, el = idx & 127;
        float s = 0.f;
#pragma unroll
        for (int jc = 0; jc < 32; jc++)
            s += g_upart[(size_t)((jc * 8 + bb) * 16 + h) * ND + e0 + el];
        us[bb][el] = s;
    }
    __syncthreads();
    float acc[8] = {0.f,0.f,0.f,0.f,0.f,0.f,0.f,0.f};
    for (int el = 0; el < 128; el += 8) {
        float w[8];
#pragma unroll
        for (int k2 = 0; k2 < 8; k2++)
            w[k2] = Wv[(e0 + el + k2) * ND + h * NDK + tid];
#pragma unroll
        for (int k2 = 0; k2 < 8; k2++)
#pragma unroll
            for (int bb = 0; bb < 8; bb++) acc[bb] = fmaf(w[k2], us[bb][el + k2], acc[bb]);
    }
#pragma unroll
    for (int bb = 0; bb < 8; bb++)
        g_xpart[(blockIdx.x * 8 + bb) * ND + h * NDK + tid] = acc[bb];
}

__global__ void k_xred(const float* __restrict__ bv) {
    int i = blockIdx.x * 256 + threadIdx.x;
    int c = i & (ND - 1), b = i >> 11;
    float s = bv[c];
#pragma unroll
    for (int ec = 0; ec < 16; ec++) s += g_xpart[(ec * 8 + b) * ND + c];
    g_x[i] = s;
}

// ---------------- K8: out partials = x @ Wo, g-split 16, MLP 8 ----------------
__global__ __launch_bounds__(256) void k_out(const float* __restrict__ Wo) {
    int tid = threadIdx.x;
    int f = blockIdx.x * 256 + tid;
    int g0 = blockIdx.y * 128;
    __shared__ float xs[8][128];
    for (int idx = tid; idx < 1024; idx += 256)
        xs[idx >> 7][idx & 127] = g_x[(idx >> 7) * ND + g0 + (idx & 127)];
    __syncthreads();
    float acc[8] = {0.f,0.f,0.f,0.f,0.f,0.f,0.f,0.f};
    for (int g = 0; g < 128; g += 8) {
        float w[8];
#pragma unroll
        for (int k2 = 0; k2 < 8; k2++) w[k2] = Wo[(g0 + g + k2) * ND + f];
#pragma unroll
        for (int k2 = 0; k2 < 8; k2++)
#pragma unroll
            for (int b = 0; b < 8; b++) acc[b] = fmaf(w[k2], xs[b][g + k2], acc[b]);
    }
#pragma unroll
    for (int b = 0; b < 8; b++) g_opart[(blockIdx.y * 8 + b) * ND + f] = acc[b];
}

__global__ void k_ored(const float* __restrict__ bo, float* __restrict__ out) {
    int i = blockIdx.x * 256 + threadIdx.x;
    int c = i & (ND - 1), b = i >> 11;
    float s = bo[c];
#pragma unroll
    for (int gc = 0; gc < 16; gc++) s += g_opart[(gc * 8 + b) * ND + c];
    out[i] = s;
}

extern "C" void kernel_launch(void* const* d_in, const int* in_sizes, int n_in,
                              void* d_out, int out_size) {
    const float* query   = (const float*)d_in[0];
    const float* key     = (const float*)d_in[1];
    const float* value   = (const float*)d_in[2];
    const float* Wq      = (const float*)d_in[3];
    const float* Wk      = (const float*)d_in[4];
    const float* Wv      = (const float*)d_in[5];
    const float* bv      = (const float*)d_in[6];
    const float* Wo      = (const float*)d_in[7];
    const float* bo      = (const float*)d_in[8];
    const float* key_pos = (const float*)d_in[9];
    const float* q_bias  = (const float*)d_in[10];
    float* out = (float*)d_out;

    // k_scores kept at launch idx 3 so the profiler's fixed slot lands on it.
    k_qbp    <<<dim3(8, 16),     256>>>(query, Wq);
    k_qb     <<<64,              256>>>(q_bias);
    k_A      <<<dim3(16, 16),    128>>>(Wk);
    k_scores <<<dim3(128, 8),    512>>>(key);
    k_pos    <<<dim3(1024, 2),   256>>>(key_pos);
    k_softmax<<<128,             256>>>();
    k_value  <<<dim3(2, 8, 32),  256>>>(value);
    k_projv  <<<dim3(16, 16),    128>>>(Wv);
    k_xred   <<<64,              256>>>(bv);
    k_out    <<<dim3(8, 16),     256>>>(Wo);
    k_ored   <<<64,              256>>>(bo, out);
}